// round 5
// baseline (speedup 1.0000x reference)
#include <cuda_runtime.h>

#define NB 16
#define NS 65
#define NR 1040          // NB * NS
#define NW 256
#define ND 128
#define NT 2176          // MAX_LEN_PAD
#define OUT_T 2048
#define MIN_SEG 32

// scratch (device globals: allocation-free)
__device__ int g_rowstart[NR + 1];
__device__ int g_offset[NR];
__device__ int g_meta[2];   // [0]=L, [1]=Lc

// ---------------------------------------------------------------------------
// Kernel 1: per-row counts + exclusive prefix (rowstart), segment offsets, L.
// Mask within a row is a prefix in w (floor(w/sc) monotone in w), so count is
// found by binary search using the EXACT float ops of the reference.
// ---------------------------------------------------------------------------
__global__ void __launch_bounds__(1024, 1)
prep_kernel(const float* __restrict__ scales,
            const int*   __restrict__ len_seq,
            const int*   __restrict__ len_seg_raw) {
    __shared__ int s_len[NR];
    __shared__ int s_off[NR];
    __shared__ int s_cnt[NR];
    __shared__ int s_chtot[NB];
    const int tid = threadIdx.x;

    for (int r = tid; r < NR; r += 1024)
        s_len[r] = len_seg_raw[r] + MIN_SEG;
    __syncthreads();

    // per-batch exclusive cumsum of segment lengths
    if (tid < NB) {
        int run = 0, base = tid * NS;
        #pragma unroll 1
        for (int s = 0; s < NS; s++) { s_off[base + s] = run; run += s_len[base + s]; }
    }
    __syncthreads();

    // per-row masked-prefix count via binary search (exact reference predicate)
    for (int r = tid; r < NR; r += 1024) {
        const float sc   = scales[r] + 0.5f;
        const float m1   = (float)s_len[r] - 1.0f;             // len_seg - 1
        const float offf = (float)s_off[r];
        const float lsq  = (float)len_seq[r / NS] - 1.0f;      // len_seq - 1
        int lo = 0, hi = NW;
        while (lo < hi) {
            const int mid = (lo + hi) >> 1;
            const float fls = floorf((float)mid / sc);
            const bool m = (fls < m1) && ((fls + offf) < lsq);
            if (m) lo = mid + 1; else hi = mid;
        }
        s_cnt[r]    = lo;
        g_offset[r] = s_off[r];
    }
    __syncthreads();

    // chunked exclusive scan of counts: 16 chunks x 65
    if (tid < NB) {
        int base = tid * NS, run = 0;
        #pragma unroll 1
        for (int j = 0; j < NS; j++) { int c = s_cnt[base + j]; s_cnt[base + j] = run; run += c; }
        s_chtot[tid] = run;
    }
    __syncthreads();
    if (tid == 0) {
        int run = 0;
        #pragma unroll
        for (int i = 0; i < NB; i++) { int c = s_chtot[i]; s_chtot[i] = run; run += c; }
        const int total = run;
        const int L = total / NB;
        g_rowstart[NR] = total;
        g_meta[0] = L;
        g_meta[1] = (L < OUT_T) ? L : OUT_T;
    }
    __syncthreads();
    for (int r = tid; r < NR; r += 1024)
        g_rowstart[r] = s_cnt[r] + s_chtot[r / NS];
}

// ---------------------------------------------------------------------------
// Kernel 2: one warp per output row (b, t). Warp-ballot 2-level search of
// rowstart (smem), lerp two x rows with float4, write float4.
// Zero-fill t >= Lc.
// ---------------------------------------------------------------------------
__global__ void __launch_bounds__(256)
gather_kernel(const float* __restrict__ x,
              const float* __restrict__ scales,
              float*       __restrict__ out) {
    __shared__ int s_rs[NR + 33];   // padded so level-2 probes never go OOB
    const int tid = threadIdx.x;
    const int L  = g_meta[0];
    const int Lc = g_meta[1];
    for (int i = tid; i < NR + 33; i += 256) {
        int v = (i <= NR) ? g_rowstart[i] : 0x7fffffff;
        s_rs[i] = v;
    }
    __syncthreads();

    const int warp = tid >> 5;
    const int lane = tid & 31;
    const int q = blockIdx.x * 8 + warp;      // output row in [0, 16*2048)
    const int b = q >> 11;
    const int t = q & (OUT_T - 1);

    float4* orow = reinterpret_cast<float4*>(out + (size_t)q * ND) + lane;

    if (t >= Lc) {                             // tail (and L<2048 case): zeros
        *orow = make_float4(0.f, 0.f, 0.f, 0.f);
        return;
    }

    const int p = b * L + t;                   // compact index, < 16L <= total

    // 2-level 32-way search: find largest r with rowstart[r] <= p.
    // Level 1: probe entries 0,33,66,... (33-stride covers 0..1056 >= 1040).
    unsigned bal = __ballot_sync(0xffffffffu, s_rs[lane * 33] <= p);
    const int c1 = 31 - __clz(bal);            // bal has bit0 set (rs[0]=0<=p)
    const int base = c1 * 33;
    // Level 2: probe base..base+32 (33 entries; lane covers base+1..base+32,
    // base itself is known <= p).
    bal = __ballot_sync(0xffffffffu, s_rs[base + 1 + lane] <= p);
    const int r = base + (32 - __clz(bal));    // __clz(0)=32 -> r=base
    const int w = p - s_rs[r];

    const float sc  = __ldg(scales + r) + 0.5f;
    const float qs  = (float)w / sc;           // same f32 div as reference
    const float fls = floorf(qs);
    const float lam = qs - fls;

    int i0 = (int)fls + g_offset[r];
    if (i0 > NT - 1) i0 = NT - 1;
    int i1 = i0 + 1;
    if (i1 > NT - 1) i1 = NT - 1;
    const int bsrc = r / NS;

    const float4* p0 = reinterpret_cast<const float4*>(
        x + ((size_t)bsrc * NT + (size_t)i0) * ND) + lane;
    const float4* p1 = reinterpret_cast<const float4*>(
        x + ((size_t)bsrc * NT + (size_t)i1) * ND) + lane;
    const float4 a = __ldg(p0);
    const float4 c = __ldg(p1);

    const float om = 1.0f - lam;
    float4 y;
    y.x = om * a.x + lam * c.x;
    y.y = om * a.y + lam * c.y;
    y.z = om * a.z + lam * c.z;
    y.w = om * a.w + lam * c.w;
    *orow = y;
}

extern "C" void kernel_launch(void* const* d_in, const int* in_sizes, int n_in,
                              void* d_out, int out_size) {
    const float* x           = (const float*)d_in[0];
    const float* scales      = (const float*)d_in[1];
    const int*   len_seq     = (const int*)d_in[2];
    const int*   len_seg_raw = (const int*)d_in[3];
    float* out = (float*)d_out;

    prep_kernel<<<1, 1024>>>(scales, len_seq, len_seg_raw);
    gather_kernel<<<(NB * OUT_T) / 8, 256>>>(x, scales, out);
}

// round 8
// speedup vs baseline: 1.1453x; 1.1453x over previous
#include <cuda_runtime.h>

#define NB 16
#define NS 65
#define NR 1040          // NB * NS
#define NW 256
#define ND 128
#define NT 2176          // MAX_LEN_PAD
#define OUT_T 2048
#define MIN_SEG 32
#define RPW 4            // output rows (t) per warp in gather

// scratch (device globals: allocation-free)
__device__ int g_rowstart[NR + 1];
__device__ int g_offset[NR];
__device__ int g_meta[2];   // [0]=L, [1]=Lc

// ---------------------------------------------------------------------------
// Kernel 1: warp-parallel prep. One warp per batch does the 65-elem cumsums
// via shfl scans; counts via per-row binary search on the exact reference
// float predicate (mask is a prefix in w since floor(w/sc) is monotone).
// ---------------------------------------------------------------------------
__global__ void __launch_bounds__(1024, 1)
prep_kernel(const float* __restrict__ scales,
            const int*   __restrict__ len_seq,
            const int*   __restrict__ len_seg_raw) {
    __shared__ int s_len[NR];
    __shared__ int s_off[NR];
    __shared__ int s_cnt[NR];
    __shared__ int s_chtot[NB];
    const int tid  = threadIdx.x;
    const int wid  = tid >> 5;
    const int lane = tid & 31;

    for (int r = tid; r < NR; r += 1024)
        s_len[r] = len_seg_raw[r] + MIN_SEG;
    __syncthreads();

    // per-batch exclusive cumsum of segment lengths: warp b scans batch b
    if (wid < NB) {
        const int base = wid * NS;
        int carry = 0;
        #pragma unroll
        for (int j = 0; j < NS; j += 32) {
            const int i = j + lane;
            const int orig = (i < NS) ? s_len[base + i] : 0;
            int v = orig;
            #pragma unroll
            for (int d = 1; d < 32; d <<= 1) {
                const int n = __shfl_up_sync(0xffffffffu, v, d);
                if (lane >= d) v += n;
            }
            if (i < NS) s_off[base + i] = carry + v - orig;   // exclusive
            carry += __shfl_sync(0xffffffffu, v, 31);
        }
    }
    __syncthreads();

    // per-row masked-prefix count via binary search (exact reference predicate)
    for (int r = tid; r < NR; r += 1024) {
        const float sc   = scales[r] + 0.5f;
        const float m1   = (float)s_len[r] - 1.0f;             // len_seg - 1
        const float offf = (float)s_off[r];
        const float lsq  = (float)len_seq[r / NS] - 1.0f;      // len_seq - 1
        int lo = 0, hi = NW;
        while (lo < hi) {
            const int mid = (lo + hi) >> 1;
            const float fls = floorf((float)mid / sc);
            const bool m = (fls < m1) && ((fls + offf) < lsq);
            if (m) lo = mid + 1; else hi = mid;
        }
        s_cnt[r]    = lo;
        g_offset[r] = s_off[r];
    }
    __syncthreads();

    // per-batch exclusive scan of counts: warp b scans batch b
    if (wid < NB) {
        const int base = wid * NS;
        int carry = 0;
        #pragma unroll
        for (int j = 0; j < NS; j += 32) {
            const int i = j + lane;
            const int orig = (i < NS) ? s_cnt[base + i] : 0;
            int v = orig;
            #pragma unroll
            for (int d = 1; d < 32; d <<= 1) {
                const int n = __shfl_up_sync(0xffffffffu, v, d);
                if (lane >= d) v += n;
            }
            if (i < NS) s_cnt[base + i] = carry + v - orig;    // exclusive
            carry += __shfl_sync(0xffffffffu, v, 31);
        }
        if (lane == 0) s_chtot[wid] = carry;
    }
    __syncthreads();

    // scan the 16 batch totals in warp 0
    if (wid == 0) {
        int v = (lane < NB) ? s_chtot[lane] : 0;
        const int orig = v;
        #pragma unroll
        for (int d = 1; d < 32; d <<= 1) {
            const int n = __shfl_up_sync(0xffffffffu, v, d);
            if (lane >= d) v += n;
        }
        if (lane < NB) s_chtot[lane] = v - orig;               // exclusive
        if (lane == NB - 1) {
            const int total = v;                               // inclusive of last
            const int L = total / NB;
            g_rowstart[NR] = total;
            g_meta[0] = L;
            g_meta[1] = (L < OUT_T) ? L : OUT_T;
        }
    }
    __syncthreads();
    for (int r = tid; r < NR; r += 1024)
        g_rowstart[r] = s_cnt[r] + s_chtot[r / NS];
}

// ---------------------------------------------------------------------------
// Kernel 2: one warp per RPW consecutive output rows (b, t0..t0+RPW-1).
// Ballot-search rowstart once per warp, then forward-walk (monotone).
// float4 lerp loads/stores. Zero-fill t >= Lc.
// ---------------------------------------------------------------------------
__global__ void __launch_bounds__(512)
gather_kernel(const float* __restrict__ x,
              const float* __restrict__ scales,
              float*       __restrict__ out) {
    __shared__ int   s_rs[NR + 33];   // padded so level-2 probes never go OOB
    __shared__ float s_sc[NR];
    __shared__ int   s_of[NR];
    const int tid = threadIdx.x;
    const int L  = g_meta[0];
    const int Lc = g_meta[1];
    for (int i = tid; i < NR + 33; i += 512)
        s_rs[i] = (i <= NR) ? g_rowstart[i] : 0x7fffffff;
    for (int i = tid; i < NR; i += 512) {
        s_sc[i] = scales[i] + 0.5f;
        s_of[i] = g_offset[i];
    }
    __syncthreads();

    const int warp = tid >> 5;
    const int lane = tid & 31;
    const int wg = blockIdx.x * 16 + warp;        // 0 .. 8191
    const int b  = wg >> 9;                       // 512 chunks per batch
    const int t0 = (wg & 511) * RPW;

    float4* orow = reinterpret_cast<float4*>(out) + ((size_t)(b * OUT_T + t0) * (ND / 4)) + lane;

    if (t0 >= Lc) {                               // whole chunk is zero-fill
        #pragma unroll
        for (int i = 0; i < RPW; i++) orow[i * (ND / 4)] = make_float4(0.f, 0.f, 0.f, 0.f);
        return;
    }

    const int p0 = b * L + t0;

    // 2-level 32-way search for largest r with rowstart[r] <= p0
    unsigned bal = __ballot_sync(0xffffffffu, s_rs[lane * 33] <= p0);
    const int base = (31 - __clz(bal)) * 33;
    bal = __ballot_sync(0xffffffffu, s_rs[base + 1 + lane] <= p0);
    int rcur = base + (32 - __clz(bal));          // __clz(0)=32 -> rcur=base

    const int nrow = (Lc - t0 < RPW) ? (Lc - t0) : RPW;

    float4 A[RPW], C[RPW];
    float  lam[RPW];

    #pragma unroll
    for (int i = 0; i < RPW; i++) {
        if (i < nrow) {
            const int p = p0 + i;
            while (s_rs[rcur + 1] <= p) ++rcur;   // monotone forward walk
            const int w = p - s_rs[rcur];
            const float sc  = s_sc[rcur];
            const float qs  = (float)w / sc;      // same f32 div as reference
            const float fls = floorf(qs);
            lam[i] = qs - fls;
            int i0 = (int)fls + s_of[rcur];
            if (i0 > NT - 1) i0 = NT - 1;
            int i1 = i0 + 1;
            if (i1 > NT - 1) i1 = NT - 1;
            const int bsrc = rcur / NS;
            const float4* p0p = reinterpret_cast<const float4*>(
                x + ((size_t)bsrc * NT + (size_t)i0) * ND) + lane;
            const float4* p1p = reinterpret_cast<const float4*>(
                x + ((size_t)bsrc * NT + (size_t)i1) * ND) + lane;
            A[i] = __ldg(p0p);
            C[i] = __ldg(p1p);
        }
    }

    #pragma unroll
    for (int i = 0; i < RPW; i++) {
        float4 y = make_float4(0.f, 0.f, 0.f, 0.f);
        if (i < nrow) {
            const float lm = lam[i];
            const float om = 1.0f - lm;
            y.x = om * A[i].x + lm * C[i].x;
            y.y = om * A[i].y + lm * C[i].y;
            y.z = om * A[i].z + lm * C[i].z;
            y.w = om * A[i].w + lm * C[i].w;
        }
        orow[i * (ND / 4)] = y;
    }
}

extern "C" void kernel_launch(void* const* d_in, const int* in_sizes, int n_in,
                              void* d_out, int out_size) {
    const float* x           = (const float*)d_in[0];
    const float* scales      = (const float*)d_in[1];
    const int*   len_seq     = (const int*)d_in[2];
    const int*   len_seg_raw = (const int*)d_in[3];
    float* out = (float*)d_out;

    prep_kernel<<<1, 1024>>>(scales, len_seq, len_seg_raw);
    gather_kernel<<<(NB * OUT_T) / (16 * RPW), 512>>>(x, scales, out);
}